// round 10
// baseline (speedup 1.0000x reference)
#include <cuda_runtime.h>
#include <math.h>

// ---------------------------------------------------------------------------
// AvULoss: N=2^21 rows, C=32.
// Persistent WARP-private cp.async pipeline: each warp owns a double-buffered
// 32-row x 36-float smem tile; producer == consumer == same warp, so the main
// loop has NO block barriers (only __syncwarp) and copies stay in flight
// across compute phases. Thread-per-row consumption (stride 36 -> conflict-
// free LDS.128 per quarter-warp phase), no shuffles in the loop.
//   y = x*log2e, e = 2^y; S = sum e, dot = sum e*y, emax = max e
//   conf = emax/S ; unc = ln2*(log2 S - dot/S)
//   accurate = (2^(x[lab]*log2e) == emax), x[lab] read from the smem tile
//   num = sum w*[accurate==certain], den = sum w
//   loss = -log(num/(den+1e-10) + 1e-10)
// Last-block ticket finalizes + resets accumulators (graph-replay safe).
// Labels arrive as int32 (JAX x64-disabled downcasts the int64 randint).
// ---------------------------------------------------------------------------

#define BLOCK 128
#define WARPS 4
#define RSTRIDE 36            // floats per smem row (144B: 16B-aligned, conflict-free)
#define TROWS 32              // rows per warp-tile
#define LOG2E 1.4426950408889634f
#define LN2   0.6931471805599453f

__device__ double g_acc[2];
__device__ unsigned int g_ticket = 0;

__device__ __forceinline__ float tanh_approx(float x) {
    float r;
    asm("tanh.approx.f32 %0, %1;" : "=f"(r) : "f"(x));
    return r;
}
__device__ __forceinline__ void cp_async16(float* smem_dst, const float4* gmem_src) {
    unsigned s;
    asm("{ .reg .u64 t; cvta.to.shared.u64 t, %1; cvt.u32.u64 %0, t; }"
        : "=r"(s) : "l"(smem_dst));
    asm volatile("cp.async.cg.shared.global [%0], [%1], 16;\n"
                 :: "r"(s), "l"(gmem_src) : "memory");
}
__device__ __forceinline__ void cp_commit() {
    asm volatile("cp.async.commit_group;\n" ::: "memory");
}
__device__ __forceinline__ void cp_wait1() {
    asm volatile("cp.async.wait_group 1;\n" ::: "memory");
}

__global__ __launch_bounds__(BLOCK)
void avu_kernel(const float4* __restrict__ logits4,
                const int* __restrict__ labels,
                const float* __restrict__ unc_th_p,
                float* __restrict__ out,
                int numTiles)
{
    __shared__ float sbuf[WARPS][2][TROWS * RSTRIDE];   // 36864 B
    __shared__ float sred[8];                            // 4 warps x {num, den}
    __shared__ bool s_last;

    const int tid  = threadIdx.x;
    const int wid  = tid >> 5;
    const int lane = tid & 31;
    const float th = __ldg(unc_th_p);

    int tile = blockIdx.x * WARPS + wid;
    const int tstride = gridDim.x * WARPS;

    float num = 0.f, den = 0.f;
    int cur = 0;
    int lab_cur;

    // ---- prologue: stage tile -> buffer 0, prefetch label ----
    {
        int t0 = tile < numTiles ? tile : numTiles - 1;
        const float4* src = logits4 + (size_t)t0 * (TROWS * 8);
#pragma unroll
        for (int k = 0; k < 8; ++k) {
            int i = lane + k * 32;           // float4 index within tile
            int r = i >> 3, c = i & 7;
            cp_async16(&sbuf[wid][0][r * RSTRIDE + c * 4], &src[i]);
        }
        cp_commit();
        lab_cur = labels[t0 * TROWS + lane];
    }

    while (tile < numTiles) {                // uniform across the warp
        int tnext = tile + tstride;
        int lab_next;
        {
            int tn = tnext < numTiles ? tnext : numTiles - 1;
            const float4* src = logits4 + (size_t)tn * (TROWS * 8);
#pragma unroll
            for (int k = 0; k < 8; ++k) {
                int i = lane + k * 32;
                int r = i >> 3, c = i & 7;
                cp_async16(&sbuf[wid][cur ^ 1][r * RSTRIDE + c * 4], &src[i]);
            }
            cp_commit();
            lab_next = labels[tn * TROWS + lane];
        }

        cp_wait1();                          // current tile's group complete
        __syncwarp();                        // cross-lane visibility (warp only)

        // ---- thread-per-row compute from the warp-private tile ----
        const float* rowp = &sbuf[wid][cur][lane * RSTRIDE];
        float S = 0.f, dot = 0.f, emax = 0.f;
#pragma unroll
        for (int c = 0; c < 8; ++c) {
            float4 v = *(const float4*)&rowp[c * 4];
            float xs[4] = {v.x, v.y, v.z, v.w};
#pragma unroll
            for (int j = 0; j < 4; ++j) {
                float y = xs[j] * LOG2E;
                float e = exp2f(y);
                S += e;
                dot = __fmaf_rn(e, y, dot);
                emax = fmaxf(emax, e);
            }
        }
        float xlab = rowp[lab_cur];

        float invS = __frcp_rn(S);
        float conf = emax * invS;                       // max softmax prob
        float unc  = LN2 * (__log2f(S) - dot * invS);   // predictive entropy
        float elab = exp2f(xlab * LOG2E);
        bool accurate = (elab == emax);
        bool certain  = (unc <= th);
        float t = tanh_approx(unc);
        float w = (accurate ? conf : (1.f - conf)) * (certain ? (1.f - t) : t);
        num += (accurate == certain) ? w : 0.f;         // cats ac + iu
        den += w;

        __syncwarp();                        // done reading before buffer reuse
        cur ^= 1;
        lab_cur = lab_next;
        tile = tnext;
    }

    // ---- block reduction of (num, den), once ----
#pragma unroll
    for (int o = 16; o > 0; o >>= 1) {
        num += __shfl_down_sync(0xffffffffu, num, o);
        den += __shfl_down_sync(0xffffffffu, den, o);
    }
    if (lane == 0) {
        sred[wid]     = num;
        sred[wid + 4] = den;
    }
    __syncthreads();

    if (tid < 2) {
        double s = 0.0;
#pragma unroll
        for (int wv = 0; wv < 4; ++wv) s += (double)sred[tid * 4 + wv];
        atomicAdd(&g_acc[tid], s);
        __threadfence();
    }
    __syncthreads();

    // ---- last-block finalize + reset (graph-replay deterministic) ----
    if (tid == 0) {
        unsigned int ticket = atomicAdd(&g_ticket, 1u);
        s_last = (ticket == gridDim.x - 1u);
    }
    __syncthreads();
    if (s_last && tid == 0) {
        volatile double* acc = g_acc;
        double nsum = acc[0], dsum = acc[1];
        double avu = nsum / (dsum + 1e-10);
        out[0] = (float)(-log(avu + 1e-10));
        g_acc[0] = 0.0; g_acc[1] = 0.0;
        __threadfence();
        g_ticket = 0u;
    }
}

extern "C" void kernel_launch(void* const* d_in, const int* in_sizes, int n_in,
                              void* d_out, int out_size)
{
    const float4* logits4 = (const float4*)d_in[0];
    const int*    labels  = (const int*)d_in[1];
    const float*  unc_th  = (const float*)d_in[2];
    float* out = (float*)d_out;

    const int N = in_sizes[1];               // rows (2^21)
    const int numTiles = N / TROWS;          // 65536
    int grid = 148 * 6;                      // smem-capped 6 blocks/SM
    if (grid > numTiles / WARPS) grid = numTiles / WARPS;

    avu_kernel<<<grid, BLOCK>>>(logits4, labels, unc_th, out, numTiles);
}

// round 12
// speedup vs baseline: 1.3050x; 1.3050x over previous
#include <cuda_runtime.h>
#include <math.h>

// ---------------------------------------------------------------------------
// AvULoss: N=2^21 rows, C=32. R5 skeleton (block-level cp.async double buffer,
// 128-thread blocks, 128-row tiles, stride-36 smem) + DYNAMIC WORK STEALING:
// thread 0 of each block pops the next tile from a global atomic counter, so
// tile-count quantization and cross-CTA speed spread no longer leave SMs idle
// at the tail.
//   y = x*log2e, e = 2^y; S = sum e, dot = sum e*y, emax = max e
//   conf = emax/S ; unc = ln2*(log2 S - dot/S)
//   accurate = (2^(x[lab]*log2e) == emax), x[lab] from the smem tile
//   num = sum w*[accurate==certain], den = sum w
//   loss = -log(num/(den+1e-10) + 1e-10)
// g_next starts at GRIDC and is reset by the last-ticket block, as are the
// accumulators -> graph-replay deterministic.
// Labels arrive as int32 (JAX x64-disabled downcasts the int64 randint).
// ---------------------------------------------------------------------------

#define BLOCK 128
#define TILE_ROWS 128
#define RSTRIDE 36
#define GRIDC 888                 // 148 SMs x 6 resident blocks (smem-capped)
#define LOG2E 1.4426950408889634f
#define LN2   0.6931471805599453f

__device__ double g_acc[2];
__device__ unsigned int g_ticket = 0;
__device__ unsigned int g_next = GRIDC;     // first dynamically-issued tile

__device__ __forceinline__ float tanh_approx(float x) {
    float r;
    asm("tanh.approx.f32 %0, %1;" : "=f"(r) : "f"(x));
    return r;
}
__device__ __forceinline__ void cp_async16(float* smem_dst, const float4* gmem_src) {
    unsigned s;
    asm("{ .reg .u64 t; cvta.to.shared.u64 t, %1; cvt.u32.u64 %0, t; }"
        : "=r"(s) : "l"(smem_dst));
    asm volatile("cp.async.cg.shared.global [%0], [%1], 16;\n"
                 :: "r"(s), "l"(gmem_src) : "memory");
}
__device__ __forceinline__ void cp_commit() {
    asm volatile("cp.async.commit_group;\n" ::: "memory");
}
__device__ __forceinline__ void cp_wait1() {
    asm volatile("cp.async.wait_group 1;\n" ::: "memory");
}

__global__ __launch_bounds__(BLOCK)
void avu_kernel(const float4* __restrict__ logits4,
                const int* __restrict__ labels,
                const float* __restrict__ unc_th_p,
                float* __restrict__ out,
                int numTiles)
{
    __shared__ float srow[2][TILE_ROWS * RSTRIDE];   // 36,864 B
    __shared__ float sred[8];
    __shared__ int s_next;
    __shared__ bool s_last;

    const int tid = threadIdx.x;
    const float th = __ldg(unc_th_p);

    float acc_num = 0.f, acc_den = 0.f;
    int buf = 0;

    // ---- prologue: block b owns tile b; grab the first dynamic tile ----
    int tile = blockIdx.x;                   // grid <= numTiles guaranteed
    {
        const float4* src = logits4 + (size_t)tile * (TILE_ROWS * 8);
#pragma unroll
        for (int k = 0; k < 8; ++k) {
            int i = tid + k * BLOCK;
            int r = i >> 3, c = i & 7;
            cp_async16(&srow[0][r * RSTRIDE + c * 4], &src[i]);
        }
    }
    cp_commit();
    if (tid == 0) s_next = (int)atomicAdd(&g_next, 1u);
    __syncthreads();
    int nxt = s_next;

    while (tile < numTiles) {
        // ---- prefetch the next tile (if any) into the other buffer ----
        if (nxt < numTiles) {
            const float4* src = logits4 + (size_t)nxt * (TILE_ROWS * 8);
#pragma unroll
            for (int k = 0; k < 8; ++k) {
                int i = tid + k * BLOCK;
                int r = i >> 3, c = i & 7;
                cp_async16(&srow[buf ^ 1][r * RSTRIDE + c * 4], &src[i]);
            }
        }
        cp_commit();
        if (tid == 0) s_next = (int)atomicAdd(&g_next, 1u);   // for iter+2

        int lab = labels[(size_t)tile * TILE_ROWS + tid];     // hidden by wait

        cp_wait1();                          // current tile's group complete
        __syncthreads();                     // data + s_next visible

        // ---- thread-per-row compute ----
        const float* rowp = &srow[buf][tid * RSTRIDE];
        float S = 0.f, dot = 0.f, emax = 0.f;
#pragma unroll
        for (int c = 0; c < 8; ++c) {
            float4 v = *(const float4*)&rowp[c * 4];
            float xs[4] = {v.x, v.y, v.z, v.w};
#pragma unroll
            for (int j = 0; j < 4; ++j) {
                float y = xs[j] * LOG2E;
                float e = exp2f(y);
                S += e;
                dot = __fmaf_rn(e, y, dot);
                emax = fmaxf(emax, e);
            }
        }
        float xlab = rowp[lab];

        float invS = __frcp_rn(S);
        float conf = emax * invS;                       // max softmax prob
        float unc  = LN2 * (__log2f(S) - dot * invS);   // predictive entropy
        float elab = exp2f(xlab * LOG2E);
        bool accurate = (elab == emax);
        bool certain  = (unc <= th);
        float t = tanh_approx(unc);
        float w = (accurate ? conf : (1.f - conf)) * (certain ? (1.f - t) : t);
        acc_num += (accurate == certain) ? w : 0.f;     // cats ac + iu
        acc_den += w;

        int nxt_new = s_next;                // written before the last barrier
        __syncthreads();                     // done reading buf before reuse
        buf ^= 1;
        tile = nxt;
        nxt = nxt_new;
    }

    // ---- block reduction of (num, den), once ----
#pragma unroll
    for (int o = 16; o > 0; o >>= 1) {
        acc_num += __shfl_down_sync(0xffffffffu, acc_num, o);
        acc_den += __shfl_down_sync(0xffffffffu, acc_den, o);
    }
    const int wid = tid >> 5;
    if ((tid & 31) == 0) {
        sred[wid]     = acc_num;
        sred[wid + 4] = acc_den;
    }
    __syncthreads();

    if (tid < 2) {
        double s = 0.0;
#pragma unroll
        for (int wv = 0; wv < 4; ++wv) s += (double)sred[tid * 4 + wv];
        atomicAdd(&g_acc[tid], s);
        __threadfence();
    }
    __syncthreads();

    // ---- last-block finalize + reset (graph-replay deterministic) ----
    if (tid == 0) {
        unsigned int ticket = atomicAdd(&g_ticket, 1u);
        s_last = (ticket == gridDim.x - 1u);
    }
    __syncthreads();
    if (s_last && tid == 0) {
        volatile double* acc = g_acc;
        double nsum = acc[0], dsum = acc[1];
        double avu = nsum / (dsum + 1e-10);
        out[0] = (float)(-log(avu + 1e-10));
        g_acc[0] = 0.0; g_acc[1] = 0.0;
        g_next = GRIDC;                      // reset the work queue
        __threadfence();
        g_ticket = 0u;
    }
}

extern "C" void kernel_launch(void* const* d_in, const int* in_sizes, int n_in,
                              void* d_out, int out_size)
{
    const float4* logits4 = (const float4*)d_in[0];
    const int*    labels  = (const int*)d_in[1];
    const float*  unc_th  = (const float*)d_in[2];
    float* out = (float*)d_out;

    const int N = in_sizes[1];               // rows (2^21)
    const int numTiles = N / TILE_ROWS;      // 16384
    int grid = GRIDC;
    if (grid > numTiles) grid = numTiles;    // prologue tiles stay in range

    avu_kernel<<<grid, BLOCK>>>(logits4, labels, unc_th, out, numTiles);
}